// round 3
// baseline (speedup 1.0000x reference)
#include <cuda_runtime.h>
#include <cstdint>
#include <math.h>

// Problem dims
#define T_STEPS 512
#define B_SZ    64
#define H_SZ    512
#define D_SZ    32
#define NCOL    (7*H_SZ)      // 3584 gate columns
#define NTYPE   (D_SZ+1)      // 33 event types
#define PLANE   (T_STEPS*B_SZ*H_SZ)

// Tiling: 128 blocks = 64 column-groups x 2 batch-groups.
// Block (cg,bgp): units j in [cg*8, cg*8+8), batches b in [bgp*32, bgp*32+32).
// Thread (u,b_l): computes ALL 7 gates for element (b,j) over FULL K=512,
// so phase B (gates + state update) is pure register math in the same thread.
#define NBLK    128
#define NTHR    256
#define CGROUPS 64
#define UPG     8             // units per column-group
#define BPG     32            // batches per batch-group
#define WPAD    516           // K-stride pad (4-bank skew per row, 16B-aligned)

#define W_S_FLOATS (7*UPG*WPAD)          // 28,896 floats = 115,584 B
#define H_S_FLOATS (BPG*H_SZ)            // 16,384 floats =  65,536 B
#define SMEM_BYTES ((W_S_FLOATS + H_S_FLOATS)*4)   // 181,120 B < 227 KB, > 113.5 KB

typedef unsigned long long u64;

// -------- device globals --------
__device__ float    g_tg[NTYPE*NCOL];    // type_gates = embed @ W_x + b
__device__ float    g_h[B_SZ*H_SZ];      // recurrent h state
__device__ unsigned g_arrive;
__device__ unsigned g_gen;

// ---------------- init ----------------
__global__ void hawkes_init(const float* __restrict__ embed,
                            const float* __restrict__ W,
                            const float* __restrict__ bg,
                            const float* __restrict__ h0)
{
    int idx = blockIdx.x*blockDim.x + threadIdx.x;
    if (idx == 0) { g_arrive = 0u; g_gen = 0u; }
    if (idx < B_SZ*H_SZ) g_h[idx] = h0[idx];
    if (idx < NTYPE*NCOL) {
        int ty  = idx / NCOL;
        int col = idx - ty*NCOL;
        float s = bg[col];
        #pragma unroll
        for (int d = 0; d < D_SZ; d++)
            s = fmaf(embed[ty*D_SZ + d], W[d*NCOL + col], s);
        g_tg[idx] = s;
    }
}

// ---------------- grid barrier (monotonic generation) ----------------
__device__ __forceinline__ void grid_bar(unsigned target)
{
    __threadfence();             // make this thread's g_h store visible GPU-wide
    __syncthreads();
    if (threadIdx.x == 0) {
        unsigned old = atomicAdd(&g_arrive, 1u);
        if (old == (unsigned)NBLK*target - 1u) {
            atomicExch(&g_gen, target);
        } else {
            while (*(volatile unsigned*)&g_gen < target) { __nanosleep(32); }
        }
        __threadfence();
    }
    __syncthreads();
}

__device__ __forceinline__ float sigmoidf_(float x) {
    return 1.0f / (1.0f + __expf(-x));
}

__device__ __forceinline__ void fma2(u64& acc, u64 a, u64 b) {
    asm("fma.rn.f32x2 %0, %1, %2, %0;" : "+l"(acc) : "l"(a), "l"(b));
}

// ---------------- main persistent kernel ----------------
__global__ void __launch_bounds__(NTHR, 1)
hawkes_main(const float* __restrict__ seq_dt,
            const int*   __restrict__ seq_types,
            const float* __restrict__ W,
            const float* __restrict__ c0,
            const float* __restrict__ ct0,
            float* __restrict__ out)
{
    extern __shared__ float smem[];
    float* W_s = smem;                   // [7*UPG][WPAD]
    float* h_s = smem + W_S_FLOATS;      // [BPG][H_SZ]

    const int tid = threadIdx.x;
    const int bid = blockIdx.x;
    const int cg  = bid & (CGROUPS-1);   // column group 0..63
    const int bgp = bid >> 6;            // batch group 0..1
    const int u   = tid & (UPG-1);       // unit within group 0..7
    const int b_l = tid >> 3;            // local batch 0..31

    // --- one-time: stage loop-invariant W slice ---
    // W_s[q*UPG+uu][k] = W_gates[D + k][q*H + cg*UPG + uu]
    for (int i = tid; i < 7*UPG*H_SZ; i += NTHR) {
        int q  = i / (UPG*H_SZ);
        int r  = i - q*(UPG*H_SZ);
        int uu = r >> 9;                 // / H_SZ
        int k  = r & (H_SZ-1);
        W_s[(q*UPG + uu)*WPAD + k] =
            W[(size_t)(D_SZ + k)*NCOL + q*H_SZ + cg*UPG + uu];
    }

    // --- element identity (fixed for all t) ---
    const int b_el = bgp*BPG + b_l;
    const int j_el = cg*UPG + u;
    const int e    = b_el*H_SZ + j_el;
    float c    = c0[e];
    float ctar = ct0[e];

    const float4* g_h4 = (const float4*)g_h;
    float4*       h_s4 = (float4*)h_s;

    for (int t = 0; t < T_STEPS; t++) {
        // ---- stage this batch-group's h rows [BPG][H_SZ] (L2-coherent) ----
        for (int i = tid; i < BPG*(H_SZ/4); i += NTHR) {   // 4096 float4
            int b  = i >> 7;             // /128
            int kv = i & 127;
            h_s4[b*(H_SZ/4) + kv] = __ldcg(&g_h4[(bgp*BPG + b)*(H_SZ/4) + kv]);
        }
        __syncthreads();

        // ---- full-K GEMM for (b_el, all 7 gates of unit u), f32x2 FMAs ----
        u64 acc[7];
        #pragma unroll
        for (int q = 0; q < 7; q++) acc[q] = 0ull;

        const ulonglong2* hrow = (const ulonglong2*)&h_s[b_l*H_SZ];
        #pragma unroll 2
        for (int k4 = 0; k4 < H_SZ/4; k4++) {
            ulonglong2 hv = hrow[k4];
            #pragma unroll
            for (int q = 0; q < 7; q++) {
                ulonglong2 wv = *(const ulonglong2*)&W_s[(q*UPG + u)*WPAD + k4*4];
                fma2(acc[q], hv.x, wv.x);
                fma2(acc[q], hv.y, wv.y);
            }
        }

        // ---- phase B: all in registers ----
        {
            int   ty  = __ldg(&seq_types[t*B_SZ + b_el]);
            float dtv = __ldg(&seq_dt  [t*B_SZ + b_el]);

            float g[7];
            #pragma unroll
            for (int q = 0; q < 7; q++) {
                float2 p = *reinterpret_cast<float2*>(&acc[q]);
                g[q] = p.x + p.y + __ldg(&g_tg[ty*NCOL + q*H_SZ + j_el]);
            }

            float inpt   = sigmoidf_(g[0]);
            float forget = sigmoidf_(g[1]);
            float outp   = sigmoidf_(g[2]);
            float in_tar = sigmoidf_(g[3]);
            float fg_tar = sigmoidf_(g[4]);
            float z      = tanhf(g[5]);
            float y      = 10.0f * g[6];
            float decay  = 0.1f * (fmaxf(y, 0.0f) + log1pf(__expf(-fabsf(y))));

            float c_i      = forget*c + inpt*z;
            float ctar_new = fg_tar*ctar + in_tar*z;
            float edt      = __expf(-decay*dtv);
            float c_t      = ctar_new + (c_i - ctar_new)*edt;
            float h_t      = outp * tanhf(c_t);

            c    = c_t;
            ctar = ctar_new;

            g_h[e] = h_t;

            size_t base = (size_t)t*(B_SZ*H_SZ) + e;
            out[base + 0*(size_t)PLANE] = h_t;
            out[base + 1*(size_t)PLANE] = outp;
            out[base + 2*(size_t)PLANE] = c_i;
            out[base + 3*(size_t)PLANE] = ctar_new;
            out[base + 4*(size_t)PLANE] = decay;
        }

        if (t + 1 < T_STEPS) grid_bar((unsigned)(t + 1));
    }
}

// ---------------- launch ----------------
extern "C" void kernel_launch(void* const* d_in, const int* in_sizes, int n_in,
                              void* d_out, int out_size)
{
    const float* seq_dt    = (const float*)d_in[0];
    const int*   seq_types = (const int*)  d_in[1];
    const float* embed     = (const float*)d_in[2];
    const float* W         = (const float*)d_in[3];
    const float* bg        = (const float*)d_in[4];
    const float* h0        = (const float*)d_in[5];
    const float* c0        = (const float*)d_in[6];
    const float* ct0       = (const float*)d_in[7];
    float* out = (float*)d_out;

    cudaFuncSetAttribute(hawkes_main,
                         cudaFuncAttributeMaxDynamicSharedMemorySize, SMEM_BYTES);

    hawkes_init<<<(NTYPE*NCOL + 255)/256, 256>>>(embed, W, bg, h0);
    hawkes_main<<<NBLK, NTHR, SMEM_BYTES>>>(seq_dt, seq_types, W, c0, ct0, out);
}

// round 6
// speedup vs baseline: 1.9988x; 1.9988x over previous
#include <cuda_runtime.h>
#include <cstdint>
#include <math.h>

// Problem dims
#define T_STEPS 512
#define B_SZ    64
#define H_SZ    512
#define D_SZ    32
#define NCOL    (7*H_SZ)      // 3584
#define NTYPE   (D_SZ+1)      // 33
#define PLANE   (T_STEPS*B_SZ*H_SZ)

// 128 blocks = 64 column-groups (8 units each) x 2 batch-groups (32 batches).
// In-block: 256 threads = 8 b_thr x 8 c_thr x 4 ks (K-split).
// GEMM thread tile: 7 gates x 4 batches (b = b_thr + 8i) over K slice of 128.
// Partials reduced through padded smem; phase B all in-block. One grid
// barrier per step.
#define NBLK    128
#define NTHR    256
#define CGROUPS 64
#define UPG     8
#define BPG     32
#define KSPL    4
#define KSL     (H_SZ/KSPL)   // 128
#define WPAD    516           // row stride for W_s and h_s (4-bank skew)
#define PPAD    40            // partials b-stride (conflict-free proven)

#define W_S_FLOATS (7*UPG*WPAD)        // 28,896
#define H_S_FLOATS (BPG*WPAD)          // 16,512
#define P_S_FLOATS (KSPL*7*UPG*PPAD)   // 8,960
#define SMEM_BYTES ((W_S_FLOATS + H_S_FLOATS + P_S_FLOATS)*4)  // 217,472 B

typedef unsigned long long u64;

__device__ float    g_tg[NTYPE*NCOL];
__device__ float    g_h[B_SZ*H_SZ];
__device__ unsigned g_arrive;
__device__ unsigned g_gen;

// ---------------- init ----------------
__global__ void hawkes_init(const float* __restrict__ embed,
                            const float* __restrict__ W,
                            const float* __restrict__ bg,
                            const float* __restrict__ h0)
{
    int idx = blockIdx.x*blockDim.x + threadIdx.x;
    if (idx == 0) { g_arrive = 0u; g_gen = 0u; }
    if (idx < B_SZ*H_SZ) g_h[idx] = h0[idx];
    if (idx < NTYPE*NCOL) {
        int ty  = idx / NCOL;
        int col = idx - ty*NCOL;
        float s = bg[col];
        #pragma unroll
        for (int d = 0; d < D_SZ; d++)
            s = fmaf(embed[ty*D_SZ + d], W[d*NCOL + col], s);
        g_tg[idx] = s;
    }
}

// ---------------- grid barrier ----------------
__device__ __forceinline__ void grid_bar(unsigned target)
{
    __threadfence();
    __syncthreads();
    if (threadIdx.x == 0) {
        unsigned old = atomicAdd(&g_arrive, 1u);
        if (old == (unsigned)NBLK*target - 1u) {
            atomicExch(&g_gen, target);
        } else {
            while (*(volatile unsigned*)&g_gen < target) { __nanosleep(32); }
        }
        __threadfence();
    }
    __syncthreads();
}

__device__ __forceinline__ float sigmoidf_(float x) {
    return 1.0f / (1.0f + __expf(-x));
}

__device__ __forceinline__ void fma2(u64& acc, u64 a, u64 b) {
    asm("fma.rn.f32x2 %0, %1, %2, %0;" : "+l"(acc) : "l"(a), "l"(b));
}

// ---------------- main persistent kernel ----------------
__global__ void __launch_bounds__(NTHR, 1)
hawkes_main(const float* __restrict__ seq_dt,
            const int*   __restrict__ seq_types,
            const float* __restrict__ W,
            const float* __restrict__ c0,
            const float* __restrict__ ct0,
            float* __restrict__ out)
{
    extern __shared__ float smem[];
    float* W_s  = smem;                            // [56][WPAD]
    float* h_s  = smem + W_S_FLOATS;               // [32][WPAD]
    float* part = smem + W_S_FLOATS + H_S_FLOATS;  // [4][56][PPAD]

    const int tid   = threadIdx.x;
    const int bid   = blockIdx.x;
    const int cg    = bid & (CGROUPS-1);   // 0..63
    const int bgp   = bid >> 6;            // 0..1
    const int b_thr = tid & 7;             // 0..7
    const int c_thr = (tid >> 3) & 7;      // 0..7 (unit within group)
    const int ks    = tid >> 6;            // 0..3 (K-split)

    // --- one-time: stage W slice. W_s[q*8+uu][k] = W[D+k][q*H + cg*8 + uu]
    for (int i = tid; i < 7*UPG*H_SZ; i += NTHR) {
        int q  = i / (UPG*H_SZ);
        int r  = i - q*(UPG*H_SZ);
        int uu = r >> 9;
        int k  = r & (H_SZ-1);
        W_s[(q*UPG + uu)*WPAD + k] =
            W[(size_t)(D_SZ + k)*NCOL + q*H_SZ + cg*UPG + uu];
    }

    // --- phase-B identity (fixed for all t): thread owns (b_el, j_el) ---
    const int u_pb = tid & 7;              // unit 0..7
    const int b_pb = tid >> 3;             // local batch 0..31
    const int j_el = cg*UPG + u_pb;
    const int b_el = bgp*BPG + b_pb;
    const int e    = b_el*H_SZ + j_el;
    float c    = c0[e];
    float ctar = ct0[e];

    const float4* g_h4 = (const float4*)g_h;

    for (int t = 0; t < T_STEPS; t++) {
        // ---- stage h rows [BPG][512] into padded h_s (L2-coherent) ----
        for (int i = tid; i < BPG*(H_SZ/4); i += NTHR) {   // 4096 float4
            int b  = i >> 7;
            int kv = i & 127;
            float4 v = __ldcg(&g_h4[(bgp*BPG + b)*(H_SZ/4) + kv]);
            *(float4*)&h_s[b*WPAD + kv*4] = v;
        }
        __syncthreads();

        // ---- GEMM: 7 gates x 4 batches over K slice [ks*128, ks*128+128) ----
        u64 acc[7][4];
        #pragma unroll
        for (int q = 0; q < 7; q++)
            #pragma unroll
            for (int i = 0; i < 4; i++) acc[q][i] = 0ull;

        const int kbase = ks*KSL;
        #pragma unroll 2
        for (int k4 = 0; k4 < KSL/4; k4++) {
            ulonglong2 hv[4];
            #pragma unroll
            for (int i = 0; i < 4; i++)
                hv[i] = *(const ulonglong2*)&h_s[(b_thr + 8*i)*WPAD + kbase + k4*4];
            #pragma unroll
            for (int q = 0; q < 7; q++) {
                ulonglong2 wv = *(const ulonglong2*)&W_s[(q*UPG + c_thr)*WPAD + kbase + k4*4];
                #pragma unroll
                for (int i = 0; i < 4; i++) {
                    fma2(acc[q][i], hv[i].x, wv.x);
                    fma2(acc[q][i], hv[i].y, wv.y);
                }
            }
        }

        // ---- write partials (conflict-free: bank = 8*(c&3)+b mod 32) ----
        #pragma unroll
        for (int q = 0; q < 7; q++)
            #pragma unroll
            for (int i = 0; i < 4; i++) {
                float2 p = *reinterpret_cast<float2*>(&acc[q][i]);
                part[(ks*7*UPG + q*UPG + c_thr)*PPAD + b_thr + 8*i] = p.x + p.y;
            }
        __syncthreads();

        // ---- phase B: reduce K-splits + gates + state update ----
        {
            int   ty  = __ldg(&seq_types[t*B_SZ + b_el]);
            float dtv = __ldg(&seq_dt  [t*B_SZ + b_el]);

            float g[7];
            #pragma unroll
            for (int q = 0; q < 7; q++) {
                float s = __ldg(&g_tg[ty*NCOL + q*H_SZ + j_el]);
                #pragma unroll
                for (int k2 = 0; k2 < KSPL; k2++)
                    s += part[(k2*7*UPG + q*UPG + u_pb)*PPAD + b_pb];
                g[q] = s;
            }

            float inpt   = sigmoidf_(g[0]);
            float forget = sigmoidf_(g[1]);
            float outp   = sigmoidf_(g[2]);
            float in_tar = sigmoidf_(g[3]);
            float fg_tar = sigmoidf_(g[4]);
            float z      = tanhf(g[5]);
            float y      = 10.0f * g[6];
            float decay  = 0.1f * (fmaxf(y, 0.0f) + log1pf(__expf(-fabsf(y))));

            float c_i      = forget*c + inpt*z;
            float ctar_new = fg_tar*ctar + in_tar*z;
            float edt      = __expf(-decay*dtv);
            float c_t      = ctar_new + (c_i - ctar_new)*edt;
            float h_t      = outp * tanhf(c_t);

            c    = c_t;
            ctar = ctar_new;

            g_h[e] = h_t;

            size_t base = (size_t)t*(B_SZ*H_SZ) + e;
            out[base + 0*(size_t)PLANE] = h_t;
            out[base + 1*(size_t)PLANE] = outp;
            out[base + 2*(size_t)PLANE] = c_i;
            out[base + 3*(size_t)PLANE] = ctar_new;
            out[base + 4*(size_t)PLANE] = decay;
        }

        if (t + 1 < T_STEPS) grid_bar((unsigned)(t + 1));
    }
}

// ---------------- launch ----------------
extern "C" void kernel_launch(void* const* d_in, const int* in_sizes, int n_in,
                              void* d_out, int out_size)
{
    const float* seq_dt    = (const float*)d_in[0];
    const int*   seq_types = (const int*)  d_in[1];
    const float* embed     = (const float*)d_in[2];
    const float* W         = (const float*)d_in[3];
    const float* bg        = (const float*)d_in[4];
    const float* h0        = (const float*)d_in[5];
    const float* c0        = (const float*)d_in[6];
    const float* ct0       = (const float*)d_in[7];
    float* out = (float*)d_out;

    cudaFuncSetAttribute(hawkes_main,
                         cudaFuncAttributeMaxDynamicSharedMemorySize, SMEM_BYTES);

    hawkes_init<<<(NTYPE*NCOL + 255)/256, 256>>>(embed, W, bg, h0);
    hawkes_main<<<NBLK, NTHR, SMEM_BYTES>>>(seq_dt, seq_types, W, c0, ct0, out);
}